// round 15
// baseline (speedup 1.0000x reference)
#include <cuda_runtime.h>
#include <cuda_bf16.h>
#include <mma.h>
#include <math.h>
#include <stdint.h>

using namespace nvcuda;

#define NA   50000
#define NEg  200000
#define NSg  1000000
#define HIDF 128
#define OUTF 144

// Scratch (static device globals; no allocation allowed)
__device__ float g_PA[(size_t)NA * 256];
__device__ float g_PE[(size_t)NEg * 128];
__device__ float g_agg[(size_t)2 * NEg * 64];
__device__ float g_hid[(size_t)NEg * HIDF];
// bf16 hi/lo pre-split weights (plain row-major [K][N])
__device__ __nv_bfloat16 g_W1h[240 * 128], g_W1l[240 * 128];
__device__ __nv_bfloat16 g_W2h[128 * 144], g_W2l[128 * 144];
__device__ __nv_bfloat16 g_WBh[112 * 128], g_WBl[112 * 128];

__device__ __forceinline__ float silu_f(float v) {
    return v * __fdividef(1.f, 1.f + __expf(-v));
}
// store one float4 as bf16 hi/lo pairs at AH/AL + off
__device__ __forceinline__ void store_split(__nv_bfloat16* AH, __nv_bfloat16* AL,
                                            int off, float4 v) {
    __nv_bfloat16 h0 = __float2bfloat16(v.x), h1 = __float2bfloat16(v.y);
    __nv_bfloat16 h2 = __float2bfloat16(v.z), h3 = __float2bfloat16(v.w);
    __nv_bfloat16 l0 = __float2bfloat16(v.x - __bfloat162float(h0));
    __nv_bfloat16 l1 = __float2bfloat16(v.y - __bfloat162float(h1));
    __nv_bfloat16 l2 = __float2bfloat16(v.z - __bfloat162float(h2));
    __nv_bfloat16 l3 = __float2bfloat16(v.w - __bfloat162float(h3));
    *reinterpret_cast<__nv_bfloat162*>(AH + off)     = __nv_bfloat162(h0, h1);
    *reinterpret_cast<__nv_bfloat162*>(AH + off + 2) = __nv_bfloat162(h2, h3);
    *reinterpret_cast<__nv_bfloat162*>(AL + off)     = __nv_bfloat162(l0, l1);
    *reinterpret_cast<__nv_bfloat162*>(AL + off + 2) = __nv_bfloat162(l2, l3);
}
// vectorized global reduction: one instruction, two adjacent f32 adds
__device__ __forceinline__ void red_add_v2(float* ptr, float x, float y) {
    asm volatile("red.global.add.v2.f32 [%0], {%1, %2};"
                 :: "l"(ptr), "f"(x), "f"(y) : "memory");
}

// ---------------------------------------------------------------------------
__global__ void kZero() {
    size_t i = (size_t)blockIdx.x * blockDim.x + threadIdx.x;
    size_t n4 = (size_t)2 * NEg * 64 / 4;
    if (i < n4) reinterpret_cast<float4*>(g_agg)[i] = make_float4(0.f, 0.f, 0.f, 0.f);
}

// ---------------------------------------------------------------------------
// kW: split W1/W2/WB into bf16 hi/lo
// ---------------------------------------------------------------------------
__global__ void kW(const float* __restrict__ W1, const float* __restrict__ W2,
                   const float* __restrict__ Wf, const float* __restrict__ Ws) {
    int idx = blockIdx.x * blockDim.x + threadIdx.x;
    if (idx < 240 * 128) {
        float x = W1[idx];
        __nv_bfloat16 h = __float2bfloat16(x);
        __nv_bfloat16 l = __float2bfloat16(x - __bfloat162float(h));
        g_W1h[idx] = h; g_W1l[idx] = l;
    } else if (idx < 240 * 128 + 128 * 144) {
        int j = idx - 240 * 128;
        float x = W2[j];
        __nv_bfloat16 h = __float2bfloat16(x);
        __nv_bfloat16 l = __float2bfloat16(x - __bfloat162float(h));
        g_W2h[j] = h; g_W2l[j] = l;
    } else if (idx < 240 * 128 + 128 * 144 + 112 * 128) {
        int j = idx - 240 * 128 - 128 * 144;
        int k = j >> 7, c = j & 127;
        float x = (c < 64) ? Wf[(size_t)(128 + k) * 64 + c]
                           : Ws[(size_t)(128 + k) * 64 + (c - 64)];
        __nv_bfloat16 h = __float2bfloat16(x);
        __nv_bfloat16 l = __float2bfloat16(x - __bfloat162float(h));
        g_WBh[j] = h; g_WBl[j] = l;
    }
}

// ---------------------------------------------------------------------------
// Kernel A: per-atom projections (unchanged)
// ---------------------------------------------------------------------------
__global__ __launch_bounds__(256) void kA(const float* __restrict__ atom,
                                          const float* __restrict__ Wf,
                                          const float* __restrict__ Ws) {
    int t = threadIdx.x;
    int m = t >> 6;
    int c = t & 63;
    const float* W = ((m < 2) ? Wf : Ws) + (size_t)(m & 1) * 64 * 64;
    float w[64];
#pragma unroll
    for (int k = 0; k < 64; k++) w[k] = W[k * 64 + c];

    __shared__ float xs[32][64];
    int a0 = blockIdx.x * 32;
    for (int i = t; i < 32 * 64; i += 256) {
        int a = a0 + (i >> 6);
        xs[i >> 6][i & 63] = (a < NA) ? atom[(size_t)a * 64 + (i & 63)] : 0.f;
    }
    __syncthreads();

    for (int j = 0; j < 32; j++) {
        int a = a0 + j;
        if (a >= NA) break;
        const float4* x4 = reinterpret_cast<const float4*>(xs[j]);
        float acc = 0.f;
#pragma unroll
        for (int k4 = 0; k4 < 16; k4++) {
            float4 v = x4[k4];
            acc = fmaf(v.x, w[4 * k4 + 0], acc);
            acc = fmaf(v.y, w[4 * k4 + 1], acc);
            acc = fmaf(v.z, w[4 * k4 + 2], acc);
            acc = fmaf(v.w, w[4 * k4 + 3], acc);
        }
        g_PA[(size_t)a * 256 + t] = acc;
    }
}

// ---------------------------------------------------------------------------
// kBw: PE = ef @ WB. Register-staged cross-tile pipeline (R13 form).
// ---------------------------------------------------------------------------
#define B_LDW 136
#define B_LDA 120
#define B_WH  0
#define B_WL  30464
#define B_AH  60928
#define B_AL  76288
#define B_ST  60928
#define B_SMEM 95744

__global__ __launch_bounds__(256, 2) void kBw(const float* __restrict__ ef) {
    extern __shared__ char sm[];
    __nv_bfloat16* WH = reinterpret_cast<__nv_bfloat16*>(sm + B_WH);
    __nv_bfloat16* WL = reinterpret_cast<__nv_bfloat16*>(sm + B_WL);
    __nv_bfloat16* AH = reinterpret_cast<__nv_bfloat16*>(sm + B_AH);
    __nv_bfloat16* AL = reinterpret_cast<__nv_bfloat16*>(sm + B_AL);
    float* ST = reinterpret_cast<float*>(sm + B_ST);

    int t = threadIdx.x;
    for (int i = t; i < 112 * 128; i += 256) {
        int k = i >> 7, n = i & 127;
        WH[k * B_LDW + n] = g_WBh[i];
        WL[k * B_LDW + n] = g_WBl[i];
    }

    int w = t >> 5;
    int m0 = (w & 1) * 32, n0 = (w >> 1) * 32;
    const int ntiles = NEg / 64;   // 3125

    float4 r[7];
    if (blockIdx.x < ntiles) {
#pragma unroll
        for (int i = 0; i < 7; i++) {
            int cid = t + 256 * i;
            int e = cid / 28, q = cid - e * 28;
            r[i] = *reinterpret_cast<const float4*>(
                ef + (size_t)(blockIdx.x * 64 + e) * 112 + q * 4);
        }
    }

    for (int tile = blockIdx.x; tile < ntiles; tile += gridDim.x) {
        int eb = tile * 64;
        __syncthreads();
#pragma unroll
        for (int i = 0; i < 7; i++) {
            int cid = t + 256 * i;
            int e = cid / 28, q = cid - e * 28;
            store_split(AH, AL, e * B_LDA + q * 4, r[i]);
        }
        int nt = tile + gridDim.x;
        if (nt < ntiles) {
#pragma unroll
            for (int i = 0; i < 7; i++) {
                int cid = t + 256 * i;
                int e = cid / 28, q = cid - e * 28;
                r[i] = *reinterpret_cast<const float4*>(
                    ef + (size_t)(nt * 64 + e) * 112 + q * 4);
            }
        }
        __syncthreads();

        wmma::fragment<wmma::accumulator, 16, 16, 16, float> acc[2][2];
#pragma unroll
        for (int mi = 0; mi < 2; mi++)
#pragma unroll
            for (int ni = 0; ni < 2; ni++) wmma::fill_fragment(acc[mi][ni], 0.0f);

        for (int ks = 0; ks < 7; ks++) {
            wmma::fragment<wmma::matrix_a, 16, 16, 16, __nv_bfloat16, wmma::row_major> ah[2], al[2];
            wmma::fragment<wmma::matrix_b, 16, 16, 16, __nv_bfloat16, wmma::row_major> bh[2], bl[2];
#pragma unroll
            for (int mi = 0; mi < 2; mi++) {
                wmma::load_matrix_sync(ah[mi], AH + (m0 + 16 * mi) * B_LDA + ks * 16, B_LDA);
                wmma::load_matrix_sync(al[mi], AL + (m0 + 16 * mi) * B_LDA + ks * 16, B_LDA);
            }
#pragma unroll
            for (int ni = 0; ni < 2; ni++) {
                wmma::load_matrix_sync(bh[ni], WH + (ks * 16) * B_LDW + n0 + 16 * ni, B_LDW);
                wmma::load_matrix_sync(bl[ni], WL + (ks * 16) * B_LDW + n0 + 16 * ni, B_LDW);
            }
#pragma unroll
            for (int mi = 0; mi < 2; mi++)
#pragma unroll
                for (int ni = 0; ni < 2; ni++) {
                    wmma::mma_sync(acc[mi][ni], ah[mi], bh[ni], acc[mi][ni]);
                    wmma::mma_sync(acc[mi][ni], ah[mi], bl[ni], acc[mi][ni]);
                    wmma::mma_sync(acc[mi][ni], al[mi], bh[ni], acc[mi][ni]);
                }
        }
        __syncthreads();
#pragma unroll
        for (int mi = 0; mi < 2; mi++)
#pragma unroll
            for (int ni = 0; ni < 2; ni++)
                wmma::store_matrix_sync(ST + (m0 + 16 * mi) * B_LDW + n0 + 16 * ni,
                                        acc[mi][ni], B_LDW, wmma::mem_row_major);
        __syncthreads();
        for (int cid = t; cid < 64 * 32; cid += 256) {
            int e = cid >> 5, cq = cid & 31;
            int c = cq * 4;
            float4 v = *reinterpret_cast<const float4*>(ST + e * B_LDW + c);
            *reinterpret_cast<float4*>(g_PE + (size_t)(eb + e) * 128 + c) = v;
        }
    }
}

// ---------------------------------------------------------------------------
// Kernel C (R14 form: v4 + red.v2)
// ---------------------------------------------------------------------------
__global__ __launch_bounds__(256) void kC(const int*   __restrict__ sai,
                                          const int*   __restrict__ sei,
                                          const float* __restrict__ ang,
                                          const int*   __restrict__ sidx,
                                          const float* __restrict__ dist,
                                          const float* __restrict__ Wf,
                                          const float* __restrict__ bf,
                                          const float* __restrict__ Ws,
                                          const float* __restrict__ bs) {
    __shared__ float4 sw[16][32];
    int t = threadIdx.x;
    for (int i = t; i < 512; i += 256) {
        int k = i >> 5, l = i & 31;
        float2 wf2 = reinterpret_cast<const float2*>(Wf + (size_t)(240 + k) * 64)[l];
        float2 ws2 = reinterpret_cast<const float2*>(Ws + (size_t)(240 + k) * 64)[l];
        sw[k][l] = make_float4(wf2.x, wf2.y, ws2.x, ws2.y);
    }
    __syncthreads();

    int lane = t & 31;
    float2 bfv = reinterpret_cast<const float2*>(bf)[lane];
    float2 bsv = reinterpret_cast<const float2*>(bs)[lane];

    unsigned wid = ((unsigned)blockIdx.x * blockDim.x + t) >> 5;
    unsigned nwarps = ((unsigned)gridDim.x * blockDim.x) >> 5;
    const unsigned npairs = NSg / 2;

    for (unsigned p = wid; p < npairs; p += nwarps) {
        unsigned s0 = 2 * p, s1 = 2 * p + 1;
        int i00 = sai[2 * s0], i01 = sai[2 * s0 + 1];
        int i10 = sai[2 * s1], i11 = sai[2 * s1 + 1];
        int e0 = sei[s0], e1 = sei[s1];
        int q0 = sidx[s0], q1 = sidx[s1];
        float d0 = dist[e0], d1 = dist[e1];

        const float2* pa00 = reinterpret_cast<const float2*>(g_PA + (size_t)i00 * 256);
        const float2* pa01 = reinterpret_cast<const float2*>(g_PA + (size_t)i01 * 256);
        const float2* pe0  = reinterpret_cast<const float2*>(g_PE + (size_t)e0  * 128);
        const float2* pa10 = reinterpret_cast<const float2*>(g_PA + (size_t)i10 * 256);
        const float2* pa11 = reinterpret_cast<const float2*>(g_PA + (size_t)i11 * 256);
        const float2* pe1  = reinterpret_cast<const float2*>(g_PE + (size_t)e1  * 128);

        float2 A0 = pa00[lane],      B0 = pa01[32 + lane], C0 = pe0[lane];
        float2 D0 = pa00[64 + lane], E0 = pa01[96 + lane], F0 = pe0[32 + lane];
        float2 A1 = pa10[lane],      B1 = pa11[32 + lane], C1 = pe1[lane];
        float2 D1 = pa10[64 + lane], E1 = pa11[96 + lane], F1 = pe1[32 + lane];

        float vf0x = A0.x + B0.x + C0.x + bfv.x;
        float vf0y = A0.y + B0.y + C0.y + bfv.y;
        float vs0x = D0.x + E0.x + F0.x + bsv.x;
        float vs0y = D0.y + E0.y + F0.y + bsv.y;
        float vf1x = A1.x + B1.x + C1.x + bfv.x;
        float vf1y = A1.y + B1.y + C1.y + bfv.y;
        float vs1x = D1.x + E1.x + F1.x + bsv.x;
        float vs1y = D1.y + E1.y + F1.y + bsv.y;

        const float4* ap0 = reinterpret_cast<const float4*>(ang + (size_t)s0 * 16);
        const float4* ap1 = reinterpret_cast<const float4*>(ang + (size_t)s1 * 16);

#pragma unroll
        for (int k4 = 0; k4 < 4; k4++) {
            float4 a0 = ap0[k4];
            float4 a1 = ap1[k4];
            float aa0[4] = {a0.x, a0.y, a0.z, a0.w};
            float aa1[4] = {a1.x, a1.y, a1.z, a1.w};
#pragma unroll
            for (int j = 0; j < 4; j++) {
                float4 w = sw[4 * k4 + j][lane];
                float u0 = aa0[j], u1 = aa1[j];
                vf0x = fmaf(u0, w.x, vf0x);
                vf0y = fmaf(u0, w.y, vf0y);
                vs0x = fmaf(u0, w.z, vs0x);
                vs0y = fmaf(u0, w.w, vs0y);
                vf1x = fmaf(u1, w.x, vf1x);
                vf1y = fmaf(u1, w.y, vf1y);
                vs1x = fmaf(u1, w.z, vs1x);
                vs1y = fmaf(u1, w.w, vs1y);
            }
        }

        float dec0 = __expf(-d0 * d0 * (1.0f / 18.0f));
        float dec1 = __expf(-d1 * d1 * (1.0f / 18.0f));

        float o0x = __fdividef(dec0, 1.f + __expf(-vf0x)) *
                    (fmaxf(vs0x, 0.f) + __logf(1.f + __expf(-fabsf(vs0x))));
        float o0y = __fdividef(dec0, 1.f + __expf(-vf0y)) *
                    (fmaxf(vs0y, 0.f) + __logf(1.f + __expf(-fabsf(vs0y))));
        float o1x = __fdividef(dec1, 1.f + __expf(-vf1x)) *
                    (fmaxf(vs1x, 0.f) + __logf(1.f + __expf(-fabsf(vs1x))));
        float o1y = __fdividef(dec1, 1.f + __expf(-vf1y)) *
                    (fmaxf(vs1y, 0.f) + __logf(1.f + __expf(-fabsf(vs1y))));

        red_add_v2(g_agg + (size_t)q0 * 64 + 2 * lane, o0x, o0y);
        red_add_v2(g_agg + (size_t)q1 * 64 + 2 * lane, o1x, o1y);
    }
}

// ---------------------------------------------------------------------------
// kD1w v3: hid = silu([agg|ef] @ W1 + b1). M=128 tiles, warp tile 32x64
// (4Mx2N warps, acc 2x4), K chunked 5x48, register-staged pipeline.
// SMEM: WH@0 65280, WL@65280, A base 130560: AH 12288, AL@142848 12288;
// ST@130560 (128*136*4=69632 aliases A). total 200192.
// ---------------------------------------------------------------------------
#define D1_LDW 136
#define D1_LDC 48
#define D1_WH  0
#define D1_WL  65280
#define D1_AH  130560
#define D1_AL  142848
#define D1_ST  130560
#define D1_SMEM 200192

__global__ __launch_bounds__(256) void kD1w(const float* __restrict__ ef,
                                            const float* __restrict__ b1) {
    extern __shared__ char sm[];
    __nv_bfloat16* WH = reinterpret_cast<__nv_bfloat16*>(sm + D1_WH);
    __nv_bfloat16* WL = reinterpret_cast<__nv_bfloat16*>(sm + D1_WL);
    __nv_bfloat16* AH = reinterpret_cast<__nv_bfloat16*>(sm + D1_AH);
    __nv_bfloat16* AL = reinterpret_cast<__nv_bfloat16*>(sm + D1_AL);
    float* ST = reinterpret_cast<float*>(sm + D1_ST);
    __shared__ float b1s[128];

    int t = threadIdx.x;
    for (int i = t; i < 240 * 128; i += 256) {
        int k = i >> 7, n = i & 127;
        WH[k * D1_LDW + n] = g_W1h[i];
        WL[k * D1_LDW + n] = g_W1l[i];
    }
    if (t < 128) b1s[t] = b1[t];

    int w = t >> 5;
    int m0 = (w & 3) * 32, n0 = (w >> 2) * 64;
    const int ntiles = (NEg + 127) / 128;   // 1563 (last tile partial: 64 rows)

    // chunk: 128 rows x 12 quads (48 floats) = 6 float4/thread
    float4 r[6];
    auto load_chunk = [&](int eb2, int c2) {
#pragma unroll
        for (int i = 0; i < 6; i++) {
            int cid = t + 256 * i;
            int e = cid / 12, q = cid - e * 12;
            int row = eb2 + e; if (row >= NEg) row = NEg - 1;
            int k0 = c2 * 48 + q * 4;
            const float* src = (k0 < 128)
                ? (g_agg + (size_t)row * 128 + k0)
                : (ef + (size_t)row * 112 + (k0 - 128));
            r[i] = *reinterpret_cast<const float4*>(src);
        }
    };

    if (blockIdx.x < ntiles) load_chunk(blockIdx.x * 128, 0);

    for (int tile = blockIdx.x; tile < ntiles; tile += gridDim.x) {
        int eb = tile * 128;

        wmma::fragment<wmma::accumulator, 16, 16, 16, float> acc[2][4];
#pragma unroll
        for (int mi = 0; mi < 2; mi++)
#pragma unroll
            for (int ni = 0; ni < 4; ni++) wmma::fill_fragment(acc[mi][ni], 0.0f);

        for (int c = 0; c < 5; c++) {
            __syncthreads();   // buffer free (prev MMA / prev epilogue done)
#pragma unroll
            for (int i = 0; i < 6; i++) {
                int cid = t + 256 * i;
                int e = cid / 12, q = cid - e * 12;
                store_split(AH, AL, e * D1_LDC + q * 4, r[i]);
            }
            int nc = c + 1, ntile = tile;
            if (nc == 5) { nc = 0; ntile = tile + gridDim.x; }
            if (ntile < ntiles) load_chunk(ntile * 128, nc);
            __syncthreads();

            for (int ks = 0; ks < 3; ks++) {
                int kg = c * 3 + ks;
                wmma::fragment<wmma::matrix_a, 16, 16, 16, __nv_bfloat16, wmma::row_major> ah[2], al[2];
#pragma unroll
                for (int mi = 0; mi < 2; mi++) {
                    wmma::load_matrix_sync(ah[mi], AH + (m0 + 16 * mi) * D1_LDC + ks * 16, D1_LDC);
                    wmma::load_matrix_sync(al[mi], AL + (m0 + 16 * mi) * D1_LDC + ks * 16, D1_LDC);
                }
#pragma unroll
                for (int ni = 0; ni < 4; ni++) {
                    wmma::fragment<wmma::matrix_b, 16, 16, 16, __nv_bfloat16, wmma::row_major> bh, bl;
                    wmma::load_matrix_sync(bh, WH + (kg * 16) * D1_LDW + n0 + 16 * ni, D1_LDW);
                    wmma::load_matrix_sync(bl, WL + (kg * 16) * D1_LDW + n0 + 16 * ni, D1_LDW);
#pragma unroll
                    for (int mi = 0; mi < 2; mi++) {
                        wmma::mma_sync(acc[mi][ni], ah[mi], bh, acc[mi][ni]);
                        wmma::mma_sync(acc[mi][ni], ah[mi], bl, acc[mi][ni]);
                        wmma::mma_sync(acc[mi][ni], al[mi], bh, acc[mi][ni]);
                    }
                }
            }
        }
        __syncthreads();   // last chunk's A reads done; ST aliases buffer
#pragma unroll
        for (int mi = 0; mi < 2; mi++)
#pragma unroll
            for (int ni = 0; ni < 4; ni++)
                wmma::store_matrix_sync(ST + (m0 + 16 * mi) * D1_LDW + n0 + 16 * ni,
                                        acc[mi][ni], D1_LDW, wmma::mem_row_major);
        __syncthreads();
        for (int cid = t; cid < 128 * 32; cid += 256) {
            int e = cid >> 5, cq = cid & 31;
            int c = cq * 4;
            if (eb + e < NEg) {
                float4 v = *reinterpret_cast<const float4*>(ST + e * D1_LDW + c);
                float4 o;
                o.x = silu_f(v.x + b1s[c + 0]);
                o.y = silu_f(v.y + b1s[c + 1]);
                o.z = silu_f(v.z + b1s[c + 2]);
                o.w = silu_f(v.w + b1s[c + 3]);
                *reinterpret_cast<float4*>(g_hid + (size_t)(eb + e) * 128 + c) = o;
            }
        }
    }
}

// ---------------------------------------------------------------------------
// kD2w: out = hid @ W2 + b2. K chunked 2x64, reg-staged (R13). 2 CTAs/SM.
// ---------------------------------------------------------------------------
#define D2_LDW 152
#define D2_LDC 64
#define D2_WH  0
#define D2_WL  38912
#define D2_AH  77824
#define D2_AL  86016
#define D2_ST  77824
#define D2_SMEM 114688

__global__ __launch_bounds__(256, 2) void kD2w(const float* __restrict__ b2,
                                               float* __restrict__ out) {
    extern __shared__ char sm[];
    __nv_bfloat16* WH = reinterpret_cast<__nv_bfloat16*>(sm + D2_WH);
    __nv_bfloat16* WL = reinterpret_cast<__nv_bfloat16*>(sm + D2_WL);
    __nv_bfloat16* AH = reinterpret_cast<__nv_bfloat16*>(sm + D2_AH);
    __nv_bfloat16* AL = reinterpret_cast<__nv_bfloat16*>(sm + D2_AL);
    float* ST = reinterpret_cast<float*>(sm + D2_ST);
    __shared__ float b2s[144];

    int t = threadIdx.x;
    for (int i = t; i < 128 * 144; i += 256) {
        int k = i / 144, n = i - k * 144;
        WH[k * D2_LDW + n] = g_W2h[i];
        WL[k * D2_LDW + n] = g_W2l[i];
    }
    if (t < 144) b2s[t] = b2[t];

    int w = t >> 5;
    int m0 = (w & 3) * 16;
    int nh = w >> 2;
    int nfr = nh ? 4 : 5;
    int nbase = nh ? 80 : 0;
    const int ntiles = NEg / 64;

    float4 r[4];
    auto load_chunk = [&](int eb2, int c2) {
#pragma unroll
        for (int i = 0; i < 4; i++) {
            int cid = t + 256 * i;
            int e = cid >> 4, q = cid & 15;
            r[i] = *reinterpret_cast<const float4*>(
                g_hid + (size_t)(eb2 + e) * 128 + c2 * 64 + q * 4);
        }
    };

    if (blockIdx.x < ntiles) load_chunk(blockIdx.x * 64, 0);

    for (int tile = blockIdx.x; tile < ntiles; tile += gridDim.x) {
        int eb = tile * 64;

        wmma::fragment<wmma::accumulator, 16, 16, 16, float> acc[5];
        for (int ni = 0; ni < 5; ni++) wmma::fill_fragment(acc[ni], 0.0f);

        for (int c = 0; c < 2; c++) {
            __syncthreads();
#pragma unroll
            for (int i = 0; i < 4; i++) {
                int cid = t + 256 * i;
                int e = cid >> 4, q = cid & 15;
                store_split(AH, AL, e * D2_LDC + q * 4, r[i]);
            }
            int nc = c + 1, ntile = tile;
            if (nc == 2) { nc = 0; ntile = tile + gridDim.x; }
            if (ntile < ntiles) load_chunk(ntile * 64, nc);
            __syncthreads();

            for (int ks = 0; ks < 4; ks++) {
                int kg = c * 4 + ks;
                wmma::fragment<wmma::matrix_a, 16, 16, 16, __nv_bfloat16, wmma::row_major> ah, al;
                wmma::load_matrix_sync(ah, AH + m0 * D2_LDC + ks * 16, D2_LDC);
                wmma::load_matrix_sync(al, AL + m0 * D2_LDC + ks * 16, D2_LDC);
                for (int ni = 0; ni < nfr; ni++) {
                    int n0 = nbase + ni * 16;
                    wmma::fragment<wmma::matrix_b, 16, 16, 16, __nv_bfloat16, wmma::row_major> bh, bl;
                    wmma::load_matrix_sync(bh, WH + (kg * 16) * D2_LDW + n0, D2_LDW);
                    wmma::load_matrix_sync(bl, WL + (kg * 16) * D2_LDW + n0, D2_LDW);
                    wmma::mma_sync(acc[ni], ah, bh, acc[ni]);
                    wmma::mma_sync(acc[ni], ah, bl, acc[ni]);
                    wmma::mma_sync(acc[ni], al, bh, acc[ni]);
                }
            }
        }
        __syncthreads();
        for (int ni = 0; ni < nfr; ni++)
            wmma::store_matrix_sync(ST + m0 * 144 + nbase + ni * 16,
                                    acc[ni], 144, wmma::mem_row_major);
        __syncthreads();
        for (int cid = t; cid < 64 * 36; cid += 256) {
            int e = cid / 36, cq = cid - e * 36;
            int c = cq * 4;
            float4 v = *reinterpret_cast<const float4*>(ST + e * 144 + c);
            float4 o;
            o.x = v.x + b2s[c + 0];
            o.y = v.y + b2s[c + 1];
            o.z = v.z + b2s[c + 2];
            o.w = v.w + b2s[c + 3];
            *reinterpret_cast<float4*>(out + (size_t)(eb + e) * 144 + c) = o;
        }
    }
}

// ---------------------------------------------------------------------------
extern "C" void kernel_launch(void* const* d_in, const int* in_sizes, int n_in,
                              void* d_out, int out_size) {
    const float* atom_fea = (const float*)d_in[0];
    const float* edge_fea = (const float*)d_in[1];
    const int*   sai      = (const int*)  d_in[2];
    const int*   sei      = (const int*)  d_in[3];
    const float* ang      = (const float*)d_in[4];
    const int*   sidx     = (const int*)  d_in[5];
    const float* dist     = (const float*)d_in[6];
    const float* Wf       = (const float*)d_in[7];
    const float* bf       = (const float*)d_in[8];
    const float* Ws       = (const float*)d_in[9];
    const float* bs       = (const float*)d_in[10];
    const float* W1       = (const float*)d_in[11];
    const float* b1       = (const float*)d_in[12];
    const float* W2       = (const float*)d_in[13];
    const float* b2       = (const float*)d_in[14];
    float* out = (float*)d_out;

    static bool attr_done = false;
    if (!attr_done) {
        cudaFuncSetAttribute(kBw,  cudaFuncAttributeMaxDynamicSharedMemorySize, B_SMEM);
        cudaFuncSetAttribute(kD1w, cudaFuncAttributeMaxDynamicSharedMemorySize, D1_SMEM);
        cudaFuncSetAttribute(kD2w, cudaFuncAttributeMaxDynamicSharedMemorySize, D2_SMEM);
        attr_done = true;
    }

    {
        size_t n4 = (size_t)2 * NEg * 64 / 4;
        int blocks = (int)((n4 + 255) / 256);
        kZero<<<blocks, 256>>>();
    }
    kW<<<248, 256>>>(W1, W2, Wf, Ws);
    kA<<<(NA + 31) / 32, 256>>>(atom_fea, Wf, Ws);
    kBw<<<296, 256, B_SMEM>>>(edge_fea);
    kC<<<2048, 256>>>(sai, sei, ang, sidx, dist, Wf, bf, Ws, bs);
    kD1w<<<148, 256, D1_SMEM>>>(edge_fea, b1);
    kD2w<<<296, 256, D2_SMEM>>>(b2, out);
}

// round 17
// speedup vs baseline: 1.0347x; 1.0347x over previous
#include <cuda_runtime.h>
#include <cuda_bf16.h>
#include <mma.h>
#include <math.h>
#include <stdint.h>

using namespace nvcuda;

#define NA   50000
#define NEg  200000
#define NSg  1000000
#define HIDF 128
#define OUTF 144

// Scratch (static device globals; no allocation allowed)
__device__ float g_PA[(size_t)NA * 256];
__device__ float g_PE[(size_t)NEg * 128];
__device__ float g_agg[(size_t)2 * NEg * 64];
__device__ float g_hid[(size_t)NEg * HIDF];
// bf16 hi/lo pre-split weights (plain row-major [K][N])
__device__ __nv_bfloat16 g_W1h[240 * 128], g_W1l[240 * 128];
__device__ __nv_bfloat16 g_W2h[128 * 144], g_W2l[128 * 144];
__device__ __nv_bfloat16 g_WBh[112 * 128], g_WBl[112 * 128];

__device__ __forceinline__ float silu_f(float v) {
    return v * __fdividef(1.f, 1.f + __expf(-v));
}
// store one float4 as bf16 hi/lo pairs at AH/AL + off
__device__ __forceinline__ void store_split(__nv_bfloat16* AH, __nv_bfloat16* AL,
                                            int off, float4 v) {
    __nv_bfloat16 h0 = __float2bfloat16(v.x), h1 = __float2bfloat16(v.y);
    __nv_bfloat16 h2 = __float2bfloat16(v.z), h3 = __float2bfloat16(v.w);
    __nv_bfloat16 l0 = __float2bfloat16(v.x - __bfloat162float(h0));
    __nv_bfloat16 l1 = __float2bfloat16(v.y - __bfloat162float(h1));
    __nv_bfloat16 l2 = __float2bfloat16(v.z - __bfloat162float(h2));
    __nv_bfloat16 l3 = __float2bfloat16(v.w - __bfloat162float(h3));
    *reinterpret_cast<__nv_bfloat162*>(AH + off)     = __nv_bfloat162(h0, h1);
    *reinterpret_cast<__nv_bfloat162*>(AH + off + 2) = __nv_bfloat162(h2, h3);
    *reinterpret_cast<__nv_bfloat162*>(AL + off)     = __nv_bfloat162(l0, l1);
    *reinterpret_cast<__nv_bfloat162*>(AL + off + 2) = __nv_bfloat162(l2, l3);
}
// vectorized global reduction: one instruction, two adjacent f32 adds
__device__ __forceinline__ void red_add_v2(float* ptr, float x, float y) {
    asm volatile("red.global.add.v2.f32 [%0], {%1, %2};"
                 :: "l"(ptr), "f"(x), "f"(y) : "memory");
}

// ---------------------------------------------------------------------------
__global__ void kZero() {
    size_t i = (size_t)blockIdx.x * blockDim.x + threadIdx.x;
    size_t n4 = (size_t)2 * NEg * 64 / 4;
    if (i < n4) reinterpret_cast<float4*>(g_agg)[i] = make_float4(0.f, 0.f, 0.f, 0.f);
}

// ---------------------------------------------------------------------------
// kW: split W1/W2/WB into bf16 hi/lo
// ---------------------------------------------------------------------------
__global__ void kW(const float* __restrict__ W1, const float* __restrict__ W2,
                   const float* __restrict__ Wf, const float* __restrict__ Ws) {
    int idx = blockIdx.x * blockDim.x + threadIdx.x;
    if (idx < 240 * 128) {
        float x = W1[idx];
        __nv_bfloat16 h = __float2bfloat16(x);
        __nv_bfloat16 l = __float2bfloat16(x - __bfloat162float(h));
        g_W1h[idx] = h; g_W1l[idx] = l;
    } else if (idx < 240 * 128 + 128 * 144) {
        int j = idx - 240 * 128;
        float x = W2[j];
        __nv_bfloat16 h = __float2bfloat16(x);
        __nv_bfloat16 l = __float2bfloat16(x - __bfloat162float(h));
        g_W2h[j] = h; g_W2l[j] = l;
    } else if (idx < 240 * 128 + 128 * 144 + 112 * 128) {
        int j = idx - 240 * 128 - 128 * 144;
        int k = j >> 7, c = j & 127;
        float x = (c < 64) ? Wf[(size_t)(128 + k) * 64 + c]
                           : Ws[(size_t)(128 + k) * 64 + (c - 64)];
        __nv_bfloat16 h = __float2bfloat16(x);
        __nv_bfloat16 l = __float2bfloat16(x - __bfloat162float(h));
        g_WBh[j] = h; g_WBl[j] = l;
    }
}

// ---------------------------------------------------------------------------
// Kernel A: per-atom projections (unchanged)
// ---------------------------------------------------------------------------
__global__ __launch_bounds__(256) void kA(const float* __restrict__ atom,
                                          const float* __restrict__ Wf,
                                          const float* __restrict__ Ws) {
    int t = threadIdx.x;
    int m = t >> 6;
    int c = t & 63;
    const float* W = ((m < 2) ? Wf : Ws) + (size_t)(m & 1) * 64 * 64;
    float w[64];
#pragma unroll
    for (int k = 0; k < 64; k++) w[k] = W[k * 64 + c];

    __shared__ float xs[32][64];
    int a0 = blockIdx.x * 32;
    for (int i = t; i < 32 * 64; i += 256) {
        int a = a0 + (i >> 6);
        xs[i >> 6][i & 63] = (a < NA) ? atom[(size_t)a * 64 + (i & 63)] : 0.f;
    }
    __syncthreads();

    for (int j = 0; j < 32; j++) {
        int a = a0 + j;
        if (a >= NA) break;
        const float4* x4 = reinterpret_cast<const float4*>(xs[j]);
        float acc = 0.f;
#pragma unroll
        for (int k4 = 0; k4 < 16; k4++) {
            float4 v = x4[k4];
            acc = fmaf(v.x, w[4 * k4 + 0], acc);
            acc = fmaf(v.y, w[4 * k4 + 1], acc);
            acc = fmaf(v.z, w[4 * k4 + 2], acc);
            acc = fmaf(v.w, w[4 * k4 + 3], acc);
        }
        g_PA[(size_t)a * 256 + t] = acc;
    }
}

// ---------------------------------------------------------------------------
// kBw: PE = ef @ WB. Register-staged cross-tile pipeline (R13 form).
// ---------------------------------------------------------------------------
#define B_LDW 136
#define B_LDA 120
#define B_WH  0
#define B_WL  30464
#define B_AH  60928
#define B_AL  76288
#define B_ST  60928
#define B_SMEM 95744

__global__ __launch_bounds__(256, 2) void kBw(const float* __restrict__ ef) {
    extern __shared__ char sm[];
    __nv_bfloat16* WH = reinterpret_cast<__nv_bfloat16*>(sm + B_WH);
    __nv_bfloat16* WL = reinterpret_cast<__nv_bfloat16*>(sm + B_WL);
    __nv_bfloat16* AH = reinterpret_cast<__nv_bfloat16*>(sm + B_AH);
    __nv_bfloat16* AL = reinterpret_cast<__nv_bfloat16*>(sm + B_AL);
    float* ST = reinterpret_cast<float*>(sm + B_ST);

    int t = threadIdx.x;
    for (int i = t; i < 112 * 128; i += 256) {
        int k = i >> 7, n = i & 127;
        WH[k * B_LDW + n] = g_WBh[i];
        WL[k * B_LDW + n] = g_WBl[i];
    }

    int w = t >> 5;
    int m0 = (w & 1) * 32, n0 = (w >> 1) * 32;
    const int ntiles = NEg / 64;   // 3125

    float4 r[7];
    if (blockIdx.x < ntiles) {
#pragma unroll
        for (int i = 0; i < 7; i++) {
            int cid = t + 256 * i;
            int e = cid / 28, q = cid - e * 28;
            r[i] = *reinterpret_cast<const float4*>(
                ef + (size_t)(blockIdx.x * 64 + e) * 112 + q * 4);
        }
    }

    for (int tile = blockIdx.x; tile < ntiles; tile += gridDim.x) {
        int eb = tile * 64;
        __syncthreads();
#pragma unroll
        for (int i = 0; i < 7; i++) {
            int cid = t + 256 * i;
            int e = cid / 28, q = cid - e * 28;
            store_split(AH, AL, e * B_LDA + q * 4, r[i]);
        }
        int nt = tile + gridDim.x;
        if (nt < ntiles) {
#pragma unroll
            for (int i = 0; i < 7; i++) {
                int cid = t + 256 * i;
                int e = cid / 28, q = cid - e * 28;
                r[i] = *reinterpret_cast<const float4*>(
                    ef + (size_t)(nt * 64 + e) * 112 + q * 4);
            }
        }
        __syncthreads();

        wmma::fragment<wmma::accumulator, 16, 16, 16, float> acc[2][2];
#pragma unroll
        for (int mi = 0; mi < 2; mi++)
#pragma unroll
            for (int ni = 0; ni < 2; ni++) wmma::fill_fragment(acc[mi][ni], 0.0f);

        for (int ks = 0; ks < 7; ks++) {
            wmma::fragment<wmma::matrix_a, 16, 16, 16, __nv_bfloat16, wmma::row_major> ah[2], al[2];
            wmma::fragment<wmma::matrix_b, 16, 16, 16, __nv_bfloat16, wmma::row_major> bh[2], bl[2];
#pragma unroll
            for (int mi = 0; mi < 2; mi++) {
                wmma::load_matrix_sync(ah[mi], AH + (m0 + 16 * mi) * B_LDA + ks * 16, B_LDA);
                wmma::load_matrix_sync(al[mi], AL + (m0 + 16 * mi) * B_LDA + ks * 16, B_LDA);
            }
#pragma unroll
            for (int ni = 0; ni < 2; ni++) {
                wmma::load_matrix_sync(bh[ni], WH + (ks * 16) * B_LDW + n0 + 16 * ni, B_LDW);
                wmma::load_matrix_sync(bl[ni], WL + (ks * 16) * B_LDW + n0 + 16 * ni, B_LDW);
            }
#pragma unroll
            for (int mi = 0; mi < 2; mi++)
#pragma unroll
                for (int ni = 0; ni < 2; ni++) {
                    wmma::mma_sync(acc[mi][ni], ah[mi], bh[ni], acc[mi][ni]);
                    wmma::mma_sync(acc[mi][ni], ah[mi], bl[ni], acc[mi][ni]);
                    wmma::mma_sync(acc[mi][ni], al[mi], bh[ni], acc[mi][ni]);
                }
        }
        __syncthreads();
#pragma unroll
        for (int mi = 0; mi < 2; mi++)
#pragma unroll
            for (int ni = 0; ni < 2; ni++)
                wmma::store_matrix_sync(ST + (m0 + 16 * mi) * B_LDW + n0 + 16 * ni,
                                        acc[mi][ni], B_LDW, wmma::mem_row_major);
        __syncthreads();
        for (int cid = t; cid < 64 * 32; cid += 256) {
            int e = cid >> 5, cq = cid & 31;
            int c = cq * 4;
            float4 v = *reinterpret_cast<const float4*>(ST + e * B_LDW + c);
            *reinterpret_cast<float4*>(g_PE + (size_t)(eb + e) * 128 + c) = v;
        }
    }
}

// ---------------------------------------------------------------------------
// Kernel C (R14 form: v4 + red.v2)
// ---------------------------------------------------------------------------
__global__ __launch_bounds__(256) void kC(const int*   __restrict__ sai,
                                          const int*   __restrict__ sei,
                                          const float* __restrict__ ang,
                                          const int*   __restrict__ sidx,
                                          const float* __restrict__ dist,
                                          const float* __restrict__ Wf,
                                          const float* __restrict__ bf,
                                          const float* __restrict__ Ws,
                                          const float* __restrict__ bs) {
    __shared__ float4 sw[16][32];
    int t = threadIdx.x;
    for (int i = t; i < 512; i += 256) {
        int k = i >> 5, l = i & 31;
        float2 wf2 = reinterpret_cast<const float2*>(Wf + (size_t)(240 + k) * 64)[l];
        float2 ws2 = reinterpret_cast<const float2*>(Ws + (size_t)(240 + k) * 64)[l];
        sw[k][l] = make_float4(wf2.x, wf2.y, ws2.x, ws2.y);
    }
    __syncthreads();

    int lane = t & 31;
    float2 bfv = reinterpret_cast<const float2*>(bf)[lane];
    float2 bsv = reinterpret_cast<const float2*>(bs)[lane];

    unsigned wid = ((unsigned)blockIdx.x * blockDim.x + t) >> 5;
    unsigned nwarps = ((unsigned)gridDim.x * blockDim.x) >> 5;
    const unsigned npairs = NSg / 2;

    for (unsigned p = wid; p < npairs; p += nwarps) {
        unsigned s0 = 2 * p, s1 = 2 * p + 1;
        int i00 = sai[2 * s0], i01 = sai[2 * s0 + 1];
        int i10 = sai[2 * s1], i11 = sai[2 * s1 + 1];
        int e0 = sei[s0], e1 = sei[s1];
        int q0 = sidx[s0], q1 = sidx[s1];
        float d0 = dist[e0], d1 = dist[e1];

        const float2* pa00 = reinterpret_cast<const float2*>(g_PA + (size_t)i00 * 256);
        const float2* pa01 = reinterpret_cast<const float2*>(g_PA + (size_t)i01 * 256);
        const float2* pe0  = reinterpret_cast<const float2*>(g_PE + (size_t)e0  * 128);
        const float2* pa10 = reinterpret_cast<const float2*>(g_PA + (size_t)i10 * 256);
        const float2* pa11 = reinterpret_cast<const float2*>(g_PA + (size_t)i11 * 256);
        const float2* pe1  = reinterpret_cast<const float2*>(g_PE + (size_t)e1  * 128);

        float2 A0 = pa00[lane],      B0 = pa01[32 + lane], C0 = pe0[lane];
        float2 D0 = pa00[64 + lane], E0 = pa01[96 + lane], F0 = pe0[32 + lane];
        float2 A1 = pa10[lane],      B1 = pa11[32 + lane], C1 = pe1[lane];
        float2 D1 = pa10[64 + lane], E1 = pa11[96 + lane], F1 = pe1[32 + lane];

        float vf0x = A0.x + B0.x + C0.x + bfv.x;
        float vf0y = A0.y + B0.y + C0.y + bfv.y;
        float vs0x = D0.x + E0.x + F0.x + bsv.x;
        float vs0y = D0.y + E0.y + F0.y + bsv.y;
        float vf1x = A1.x + B1.x + C1.x + bfv.x;
        float vf1y = A1.y + B1.y + C1.y + bfv.y;
        float vs1x = D1.x + E1.x + F1.x + bsv.x;
        float vs1y = D1.y + E1.y + F1.y + bsv.y;

        const float4* ap0 = reinterpret_cast<const float4*>(ang + (size_t)s0 * 16);
        const float4* ap1 = reinterpret_cast<const float4*>(ang + (size_t)s1 * 16);

#pragma unroll
        for (int k4 = 0; k4 < 4; k4++) {
            float4 a0 = ap0[k4];
            float4 a1 = ap1[k4];
            float aa0[4] = {a0.x, a0.y, a0.z, a0.w};
            float aa1[4] = {a1.x, a1.y, a1.z, a1.w};
#pragma unroll
            for (int j = 0; j < 4; j++) {
                float4 w = sw[4 * k4 + j][lane];
                float u0 = aa0[j], u1 = aa1[j];
                vf0x = fmaf(u0, w.x, vf0x);
                vf0y = fmaf(u0, w.y, vf0y);
                vs0x = fmaf(u0, w.z, vs0x);
                vs0y = fmaf(u0, w.w, vs0y);
                vf1x = fmaf(u1, w.x, vf1x);
                vf1y = fmaf(u1, w.y, vf1y);
                vs1x = fmaf(u1, w.z, vs1x);
                vs1y = fmaf(u1, w.w, vs1y);
            }
        }

        float dec0 = __expf(-d0 * d0 * (1.0f / 18.0f));
        float dec1 = __expf(-d1 * d1 * (1.0f / 18.0f));

        float o0x = __fdividef(dec0, 1.f + __expf(-vf0x)) *
                    (fmaxf(vs0x, 0.f) + __logf(1.f + __expf(-fabsf(vs0x))));
        float o0y = __fdividef(dec0, 1.f + __expf(-vf0y)) *
                    (fmaxf(vs0y, 0.f) + __logf(1.f + __expf(-fabsf(vs0y))));
        float o1x = __fdividef(dec1, 1.f + __expf(-vf1x)) *
                    (fmaxf(vs1x, 0.f) + __logf(1.f + __expf(-fabsf(vs1x))));
        float o1y = __fdividef(dec1, 1.f + __expf(-vf1y)) *
                    (fmaxf(vs1y, 0.f) + __logf(1.f + __expf(-fabsf(vs1y))));

        red_add_v2(g_agg + (size_t)q0 * 64 + 2 * lane, o0x, o0y);
        red_add_v2(g_agg + (size_t)q1 * 64 + 2 * lane, o1x, o1y);
    }
}

// ---------------------------------------------------------------------------
// kD1w: hid = silu([agg|ef] @ W1 + b1). K chunked 3x80, reg-staged (R13/R14).
// ---------------------------------------------------------------------------
#define D1_LDW 136
#define D1_LDC 80
#define D1_WH  0
#define D1_WL  65280
#define D1_AH  130560
#define D1_AL  140800
#define D1_ST  130560
#define D1_SMEM 165376

__global__ __launch_bounds__(256) void kD1w(const float* __restrict__ ef,
                                            const float* __restrict__ b1) {
    extern __shared__ char sm[];
    __nv_bfloat16* WH = reinterpret_cast<__nv_bfloat16*>(sm + D1_WH);
    __nv_bfloat16* WL = reinterpret_cast<__nv_bfloat16*>(sm + D1_WL);
    __nv_bfloat16* AH = reinterpret_cast<__nv_bfloat16*>(sm + D1_AH);
    __nv_bfloat16* AL = reinterpret_cast<__nv_bfloat16*>(sm + D1_AL);
    float* ST = reinterpret_cast<float*>(sm + D1_ST);
    __shared__ float b1s[128];

    int t = threadIdx.x;
    for (int i = t; i < 240 * 128; i += 256) {
        int k = i >> 7, n = i & 127;
        WH[k * D1_LDW + n] = g_W1h[i];
        WL[k * D1_LDW + n] = g_W1l[i];
    }
    if (t < 128) b1s[t] = b1[t];

    int w = t >> 5;
    int m0 = (w & 1) * 32, n0 = (w >> 1) * 32;
    const int ntiles = NEg / 64;

    float4 r[5];
    auto load_chunk = [&](int eb2, int c2) {
#pragma unroll
        for (int i = 0; i < 5; i++) {
            int cid = t + 256 * i;
            int e = cid / 20, q = cid - e * 20;
            int k0 = c2 * 80 + q * 4;
            const float* src = (k0 < 128)
                ? (g_agg + (size_t)(eb2 + e) * 128 + k0)
                : (ef + (size_t)(eb2 + e) * 112 + (k0 - 128));
            r[i] = *reinterpret_cast<const float4*>(src);
        }
    };

    if (blockIdx.x < ntiles) load_chunk(blockIdx.x * 64, 0);

    for (int tile = blockIdx.x; tile < ntiles; tile += gridDim.x) {
        int eb = tile * 64;

        wmma::fragment<wmma::accumulator, 16, 16, 16, float> acc[2][2];
#pragma unroll
        for (int mi = 0; mi < 2; mi++)
#pragma unroll
            for (int ni = 0; ni < 2; ni++) wmma::fill_fragment(acc[mi][ni], 0.0f);

        for (int c = 0; c < 3; c++) {
            __syncthreads();
#pragma unroll
            for (int i = 0; i < 5; i++) {
                int cid = t + 256 * i;
                int e = cid / 20, q = cid - e * 20;
                store_split(AH, AL, e * D1_LDC + q * 4, r[i]);
            }
            int nc = c + 1, ntile = tile;
            if (nc == 3) { nc = 0; ntile = tile + gridDim.x; }
            if (ntile < ntiles) load_chunk(ntile * 64, nc);
            __syncthreads();

            for (int ks = 0; ks < 5; ks++) {
                int kg = c * 5 + ks;
                wmma::fragment<wmma::matrix_a, 16, 16, 16, __nv_bfloat16, wmma::row_major> ah[2], al[2];
                wmma::fragment<wmma::matrix_b, 16, 16, 16, __nv_bfloat16, wmma::row_major> bh[2], bl[2];
#pragma unroll
                for (int mi = 0; mi < 2; mi++) {
                    wmma::load_matrix_sync(ah[mi], AH + (m0 + 16 * mi) * D1_LDC + ks * 16, D1_LDC);
                    wmma::load_matrix_sync(al[mi], AL + (m0 + 16 * mi) * D1_LDC + ks * 16, D1_LDC);
                }
#pragma unroll
                for (int ni = 0; ni < 2; ni++) {
                    wmma::load_matrix_sync(bh[ni], WH + (kg * 16) * D1_LDW + n0 + 16 * ni, D1_LDW);
                    wmma::load_matrix_sync(bl[ni], WL + (kg * 16) * D1_LDW + n0 + 16 * ni, D1_LDW);
                }
#pragma unroll
                for (int mi = 0; mi < 2; mi++)
#pragma unroll
                    for (int ni = 0; ni < 2; ni++) {
                        wmma::mma_sync(acc[mi][ni], ah[mi], bh[ni], acc[mi][ni]);
                        wmma::mma_sync(acc[mi][ni], ah[mi], bl[ni], acc[mi][ni]);
                        wmma::mma_sync(acc[mi][ni], al[mi], bh[ni], acc[mi][ni]);
                    }
            }
        }
        __syncthreads();
#pragma unroll
        for (int mi = 0; mi < 2; mi++)
#pragma unroll
            for (int ni = 0; ni < 2; ni++)
                wmma::store_matrix_sync(ST + (m0 + 16 * mi) * D1_LDW + n0 + 16 * ni,
                                        acc[mi][ni], D1_LDW, wmma::mem_row_major);
        __syncthreads();
        for (int cid = t; cid < 64 * 32; cid += 256) {
            int e = cid >> 5, cq = cid & 31;
            int c = cq * 4;
            float4 v = *reinterpret_cast<const float4*>(ST + e * D1_LDW + c);
            float4 o;
            o.x = silu_f(v.x + b1s[c + 0]);
            o.y = silu_f(v.y + b1s[c + 1]);
            o.z = silu_f(v.z + b1s[c + 2]);
            o.w = silu_f(v.w + b1s[c + 3]);
            *reinterpret_cast<float4*>(g_hid + (size_t)(eb + e) * 128 + c) = o;
        }
    }
}

// ---------------------------------------------------------------------------
// kD2w: out = hid @ W2 + b2. K chunked 2x64, reg-staged (R13/R14). 2 CTAs/SM.
// ---------------------------------------------------------------------------
#define D2_LDW 152
#define D2_LDC 64
#define D2_WH  0
#define D2_WL  38912
#define D2_AH  77824
#define D2_AL  86016
#define D2_ST  77824
#define D2_SMEM 114688

__global__ __launch_bounds__(256, 2) void kD2w(const float* __restrict__ b2,
                                               float* __restrict__ out) {
    extern __shared__ char sm[];
    __nv_bfloat16* WH = reinterpret_cast<__nv_bfloat16*>(sm + D2_WH);
    __nv_bfloat16* WL = reinterpret_cast<__nv_bfloat16*>(sm + D2_WL);
    __nv_bfloat16* AH = reinterpret_cast<__nv_bfloat16*>(sm + D2_AH);
    __nv_bfloat16* AL = reinterpret_cast<__nv_bfloat16*>(sm + D2_AL);
    float* ST = reinterpret_cast<float*>(sm + D2_ST);
    __shared__ float b2s[144];

    int t = threadIdx.x;
    for (int i = t; i < 128 * 144; i += 256) {
        int k = i / 144, n = i - k * 144;
        WH[k * D2_LDW + n] = g_W2h[i];
        WL[k * D2_LDW + n] = g_W2l[i];
    }
    if (t < 144) b2s[t] = b2[t];

    int w = t >> 5;
    int m0 = (w & 3) * 16;
    int nh = w >> 2;
    int nfr = nh ? 4 : 5;
    int nbase = nh ? 80 : 0;
    const int ntiles = NEg / 64;

    float4 r[4];
    auto load_chunk = [&](int eb2, int c2) {
#pragma unroll
        for (int i = 0; i < 4; i++) {
            int cid = t + 256 * i;
            int e = cid >> 4, q = cid & 15;
            r[i] = *reinterpret_cast<const float4*>(
                g_hid + (size_t)(eb2 + e) * 128 + c2 * 64 + q * 4);
        }
    };

    if (blockIdx.x < ntiles) load_chunk(blockIdx.x * 64, 0);

    for (int tile = blockIdx.x; tile < ntiles; tile += gridDim.x) {
        int eb = tile * 64;

        wmma::fragment<wmma::accumulator, 16, 16, 16, float> acc[5];
        for (int ni = 0; ni < 5; ni++) wmma::fill_fragment(acc[ni], 0.0f);

        for (int c = 0; c < 2; c++) {
            __syncthreads();
#pragma unroll
            for (int i = 0; i < 4; i++) {
                int cid = t + 256 * i;
                int e = cid >> 4, q = cid & 15;
                store_split(AH, AL, e * D2_LDC + q * 4, r[i]);
            }
            int nc = c + 1, ntile = tile;
            if (nc == 2) { nc = 0; ntile = tile + gridDim.x; }
            if (ntile < ntiles) load_chunk(ntile * 64, nc);
            __syncthreads();

            for (int ks = 0; ks < 4; ks++) {
                int kg = c * 4 + ks;
                wmma::fragment<wmma::matrix_a, 16, 16, 16, __nv_bfloat16, wmma::row_major> ah, al;
                wmma::load_matrix_sync(ah, AH + m0 * D2_LDC + ks * 16, D2_LDC);
                wmma::load_matrix_sync(al, AL + m0 * D2_LDC + ks * 16, D2_LDC);
                for (int ni = 0; ni < nfr; ni++) {
                    int n0 = nbase + ni * 16;
                    wmma::fragment<wmma::matrix_b, 16, 16, 16, __nv_bfloat16, wmma::row_major> bh, bl;
                    wmma::load_matrix_sync(bh, WH + (kg * 16) * D2_LDW + n0, D2_LDW);
                    wmma::load_matrix_sync(bl, WL + (kg * 16) * D2_LDW + n0, D2_LDW);
                    wmma::mma_sync(acc[ni], ah, bh, acc[ni]);
                    wmma::mma_sync(acc[ni], ah, bl, acc[ni]);
                    wmma::mma_sync(acc[ni], al, bh, acc[ni]);
                }
            }
        }
        __syncthreads();
        for (int ni = 0; ni < nfr; ni++)
            wmma::store_matrix_sync(ST + m0 * 144 + nbase + ni * 16,
                                    acc[ni], 144, wmma::mem_row_major);
        __syncthreads();
        for (int cid = t; cid < 64 * 36; cid += 256) {
            int e = cid / 36, cq = cid - e * 36;
            int c = cq * 4;
            float4 v = *reinterpret_cast<const float4*>(ST + e * 144 + c);
            float4 o;
            o.x = v.x + b2s[c + 0];
            o.y = v.y + b2s[c + 1];
            o.z = v.z + b2s[c + 2];
            o.w = v.w + b2s[c + 3];
            *reinterpret_cast<float4*>(out + (size_t)(eb + e) * 144 + c) = o;
        }
    }
}

// ---------------------------------------------------------------------------
extern "C" void kernel_launch(void* const* d_in, const int* in_sizes, int n_in,
                              void* d_out, int out_size) {
    const float* atom_fea = (const float*)d_in[0];
    const float* edge_fea = (const float*)d_in[1];
    const int*   sai      = (const int*)  d_in[2];
    const int*   sei      = (const int*)  d_in[3];
    const float* ang      = (const float*)d_in[4];
    const int*   sidx     = (const int*)  d_in[5];
    const float* dist     = (const float*)d_in[6];
    const float* Wf       = (const float*)d_in[7];
    const float* bf       = (const float*)d_in[8];
    const float* Ws       = (const float*)d_in[9];
    const float* bs       = (const float*)d_in[10];
    const float* W1       = (const float*)d_in[11];
    const float* b1       = (const float*)d_in[12];
    const float* W2       = (const float*)d_in[13];
    const float* b2       = (const float*)d_in[14];
    float* out = (float*)d_out;

    static bool init_done = false;
    static cudaStream_t s1, s2, s3;
    static cudaEvent_t ev0, ev1, ev2, ev3;
    if (!init_done) {
        cudaFuncSetAttribute(kBw,  cudaFuncAttributeMaxDynamicSharedMemorySize, B_SMEM);
        cudaFuncSetAttribute(kD1w, cudaFuncAttributeMaxDynamicSharedMemorySize, D1_SMEM);
        cudaFuncSetAttribute(kD2w, cudaFuncAttributeMaxDynamicSharedMemorySize, D2_SMEM);
        cudaStreamCreateWithFlags(&s1, cudaStreamNonBlocking);
        cudaStreamCreateWithFlags(&s2, cudaStreamNonBlocking);
        cudaStreamCreateWithFlags(&s3, cudaStreamNonBlocking);
        cudaEventCreateWithFlags(&ev0, cudaEventDisableTiming);
        cudaEventCreateWithFlags(&ev1, cudaEventDisableTiming);
        cudaEventCreateWithFlags(&ev2, cudaEventDisableTiming);
        cudaEventCreateWithFlags(&ev3, cudaEventDisableTiming);
        init_done = true;
    }

    // fork from the default stream
    cudaEventRecord(ev0, 0);
    cudaStreamWaitEvent(s1, ev0, 0);
    cudaStreamWaitEvent(s2, ev0, 0);
    cudaStreamWaitEvent(s3, ev0, 0);

    // s1: weight split -> kBw (needs g_WBh/g_WBl)
    kW<<<248, 256, 0, s1>>>(W1, W2, Wf, Ws);
    kBw<<<296, 256, B_SMEM, s1>>>(edge_fea);
    cudaEventRecord(ev1, s1);
    // s2: per-atom projections
    kA<<<(NA + 31) / 32, 256, 0, s2>>>(atom_fea, Wf, Ws);
    cudaEventRecord(ev2, s2);
    // s3: zero scatter buffer
    {
        size_t n4 = (size_t)2 * NEg * 64 / 4;
        int blocks = (int)((n4 + 255) / 256);
        kZero<<<blocks, 256, 0, s3>>>();
    }
    cudaEventRecord(ev3, s3);

    // join on default stream
    cudaStreamWaitEvent(0, ev1, 0);
    cudaStreamWaitEvent(0, ev2, 0);
    cudaStreamWaitEvent(0, ev3, 0);

    kC<<<2048, 256>>>(sai, sei, ang, sidx, dist, Wf, bf, Ws, bs);
    kD1w<<<148, 256, D1_SMEM>>>(edge_fea, b1);
    kD2w<<<296, 256, D2_SMEM>>>(b2, out);
}